// round 13
// baseline (speedup 1.0000x reference)
#include <cuda_runtime.h>
#include <cstdint>

#define BBATCH 4
#define SSZ 384
#define DD 300
#define EE 50
#define HH 150
#define BSR (BBATCH*SSZ)   /* 1536 */
#define D1 450
#define INVE (1.0f/50.0f)

// ---------------- device scratch ----------------
__device__ float g_we[EE];
__device__ float g_w1s[HH];
__device__ float g_w2s[HH];
__device__ float g_sbh;
__device__ float g_A0[BBATCH*SSZ*SSZ];
__device__ float g_A1[BBATCH*SSZ*SSZ];
__device__ float g_Q [BSR*HH];
__device__ float g_P [BSR*HH];
__device__ float g_OX[BSR*DD];
__device__ float g_s1[BSR];
__device__ float g_s2[BSR];
__device__ float g_c0a[BSR*HH];
__device__ float g_c0b[BSR*HH];
__device__ float g_c1a[BSR*HH];
__device__ float g_c1b[BSR*HH];

// ---------------- prep ------------------------------------------------------
__global__ void prep_weights(const float* __restrict__ Wh, const float* __restrict__ bh) {
    int t = threadIdx.x;
    const int WHC = 2*HH + EE;
    if (t < EE) {
        float s = 0.f;
        for (int f = 0; f < EE; f++) s += Wh[f*WHC + t];
        g_we[t] = s;
    }
    if (t < HH) {
        float a = 0.f, b = 0.f;
        for (int f = 0; f < EE; f++) {
            a += Wh[f*WHC + EE + t];
            b += Wh[f*WHC + EE + HH + t];
        }
        g_w1s[t] = a;
        g_w2s[t] = b;
    }
    if (t == 0) {
        float s = 0.f;
        for (int e = 0; e < EE; e++) s += bh[e];
        g_sbh = s;
    }
}

// ---- A-operand loaders (round-5 proven): 8 k-values {kq..kq+3, kq+8..kq+11} -
// ASRC 0: raw fp32 ; ASRC 1: g0 epilogue ; ASRC 2: g1 epilogue
template<int ASRC>
__device__ __forceinline__ void ldA8(float* ar, const float* __restrict__ A, int lda,
                                     const float* __restrict__ ba,
                                     int m, int kq, int K) {
    if (ASRC == 0) {
        const float* p = A + (size_t)m * lda;
        #pragma unroll
        for (int h = 0; h < 2; h++) {
            int k = kq + h*8;
            float4 v = (k < K) ? *(const float4*)(p + k) : make_float4(0.f,0.f,0.f,0.f);
            ar[h*4+0]=v.x; ar[h*4+1]=v.y; ar[h*4+2]=v.z; ar[h*4+3]=v.w;
        }
    } else {
        const float* pa = (ASRC==1) ? g_c0a : g_c1a;
        const float* pb = (ASRC==1) ? g_c0b : g_c1b;
        const float* pq = (ASRC==1) ? g_Q   : g_P;
        size_t base = (size_t)m * HH;
        #pragma unroll
        for (int h = 0; h < 2; h++) {
            #pragma unroll
            for (int t = 0; t < 2; t++) {
                int k = kq + h*8 + t*2;
                float rx = 0.f, ry = 0.f;
                if (k < K) {
                    float2 a = *(const float2*)(pa + base + k);
                    float2 b = *(const float2*)(pb + base + k);
                    float2 q = *(const float2*)(pq + base + k);
                    float2 bb = *(const float2*)(ba + k);
                    rx = fmaxf(fmaf(a.x + b.x, INVE, q.x + 2.f*bb.x), 0.f);
                    ry = fmaxf(fmaf(a.y + b.y, INVE, q.y + 2.f*bb.y), 0.f);
                }
                ar[h*4 + t*2] = rx; ar[h*4 + t*2 + 1] = ry;
            }
        }
    }
}

// ======= 16-chunk core (round-5, static smem) — used ONLY in stage1 =========
template<int ASRC>
__device__ __forceinline__ void ntB16(
    const float* __restrict__ A, int lda, int K,
    const float* __restrict__ baA,
    const float* __restrict__ W, int ldw, int N,
    int m0, int n0,
    const float* __restrict__ biasC, const float* __restrict__ Cadd,
    float* __restrict__ C, int ldc)
{
    __shared__ __align__(16) float As[16][68];
    __shared__ __align__(16) float Ws[16][36];
    int tid = threadIdx.x;
    int arow = tid >> 1, aq = (tid & 1) * 4;
    int wrow = tid >> 2, wq = (tid & 3) * 2;
    int tx = tid & 7, ty = tid >> 3;
    int NIT = (K + 15) >> 4;

    int mA = m0 + arow;
    int nW = n0 + wrow;
    bool nok = nW < N;
    const float* Wrow = W + (size_t)(nok ? nW : 0) * ldw;

    float ar[8], wr[4];
    float acc[4][4] = {};

    ldA8<ASRC>(ar, A, lda, baA, mA, aq, K);
    #pragma unroll
    for (int h = 0; h < 2; h++) {
        int k = wq + h*8;
        float2 v = (nok && k < K) ? *(const float2*)(Wrow + k) : make_float2(0.f,0.f);
        wr[h*2] = v.x; wr[h*2+1] = v.y;
    }

    for (int it = 0; it < NIT; it++) {
        __syncthreads();
        #pragma unroll
        for (int h = 0; h < 2; h++)
            #pragma unroll
            for (int j = 0; j < 4; j++)
                As[aq + h*8 + j][arow] = ar[h*4 + j];
        #pragma unroll
        for (int h = 0; h < 2; h++)
            #pragma unroll
            for (int j = 0; j < 2; j++)
                Ws[wq + h*8 + j][wrow] = wr[h*2 + j];
        __syncthreads();
        if (it + 1 < NIT) {
            int k0 = (it + 1) * 16;
            ldA8<ASRC>(ar, A, lda, baA, mA, k0 + aq, K);
            #pragma unroll
            for (int h = 0; h < 2; h++) {
                int k = k0 + wq + h*8;
                float2 v = (nok && k < K) ? *(const float2*)(Wrow + k) : make_float2(0.f,0.f);
                wr[h*2] = v.x; wr[h*2+1] = v.y;
            }
        }
        #pragma unroll
        for (int kk = 0; kk < 16; kk++) {
            float4 a = *(const float4*)&As[kk][ty*4];
            float4 w = *(const float4*)&Ws[kk][tx*4];
            float am[4] = {a.x,a.y,a.z,a.w};
            float wm[4] = {w.x,w.y,w.z,w.w};
            #pragma unroll
            for (int i = 0; i < 4; i++)
                #pragma unroll
                for (int j = 0; j < 4; j++)
                    acc[i][j] = fmaf(am[i], wm[j], acc[i][j]);
        }
    }

    #pragma unroll
    for (int i = 0; i < 4; i++) {
        int m = m0 + ty*4 + i;
        #pragma unroll
        for (int j = 0; j < 4; j++) {
            int n = n0 + tx*4 + j;
            if (n < N) {
                float v = acc[i][j];
                if (biasC) v += biasC[n];
                if (Cadd) v += Cadd[(size_t)m*ldc + n];
                C[(size_t)m*ldc + n] = v;
            }
        }
    }
}

// ======= BIG core: whole-K smem-resident, ONE sync, zero syncs in compute ===
// SK = smem K capacity (multiple of 16, >= K). Dynamic smem:
//   As[SK][68] at offset 0, Ws[SK][36] at offset SK*68*4.
template<int ASRC, int SK>
__device__ __forceinline__ void ntBig(
    const float* __restrict__ A, int lda, int K,
    const float* __restrict__ baA,
    const float* __restrict__ W, int ldw, int N,
    int m0, int n0,
    const float* __restrict__ biasC, const float* __restrict__ Cadd,
    float* __restrict__ C, int ldc)
{
    extern __shared__ __align__(16) float dsm[];
    float (*As)[68] = (float(*)[68])dsm;
    float (*Ws)[36] = (float(*)[36])(dsm + SK*68);
    int tid = threadIdx.x;
    int arow = tid >> 1, aq = (tid & 1) * 4;
    int wrow = tid >> 2, wq = (tid & 3) * 2;
    int tx = tid & 7, ty = tid >> 3;
    const int NIT = (K + 15) >> 4;

    int mA = m0 + arow;
    int nW = n0 + wrow;
    bool nok = nW < N;
    const float* Wrow = W + (size_t)(nok ? nW : 0) * ldw;

    // ---- load phase: all chunks, no syncs between ----
    for (int it = 0; it < NIT; it++) {
        int k0 = it * 16;
        float ar[8], wr[4];
        ldA8<ASRC>(ar, A, lda, baA, mA, k0 + aq, K);
        #pragma unroll
        for (int h = 0; h < 2; h++) {
            int k = k0 + wq + h*8;
            float2 v = (nok && k < K) ? *(const float2*)(Wrow + k) : make_float2(0.f,0.f);
            wr[h*2] = v.x; wr[h*2+1] = v.y;
        }
        #pragma unroll
        for (int h = 0; h < 2; h++)
            #pragma unroll
            for (int j = 0; j < 4; j++)
                As[k0 + aq + h*8 + j][arow] = ar[h*4 + j];
        #pragma unroll
        for (int h = 0; h < 2; h++)
            #pragma unroll
            for (int j = 0; j < 2; j++)
                Ws[k0 + wq + h*8 + j][wrow] = wr[h*2 + j];
    }
    __syncthreads();

    // ---- compute phase: pure smem + FMA ----
    float acc[4][4] = {};
    int KTOT = NIT * 16;
    for (int kk = 0; kk < KTOT; kk++) {
        float4 a = *(const float4*)&As[kk][ty*4];
        float4 w = *(const float4*)&Ws[kk][tx*4];
        float am[4] = {a.x,a.y,a.z,a.w};
        float wm[4] = {w.x,w.y,w.z,w.w};
        #pragma unroll
        for (int i = 0; i < 4; i++)
            #pragma unroll
            for (int j = 0; j < 4; j++)
                acc[i][j] = fmaf(am[i], wm[j], acc[i][j]);
    }

    #pragma unroll
    for (int i = 0; i < 4; i++) {
        int m = m0 + ty*4 + i;
        #pragma unroll
        for (int j = 0; j < 4; j++) {
            int n = n0 + tx*4 + j;
            if (n < N) {
                float v = acc[i][j];
                if (biasC) v += biasC[n];
                if (Cadd) v += Cadd[(size_t)m*ldc + n];
                C[(size_t)m*ldc + n] = v;
            }
        }
    }
}

// ======= stage1: adj reduction FIRST, then Q, PX, OX GEMMs ==================
#define QB 120
#define PXB 120
#define OXB 240
#define GEMMB (QB+PXB+OXB)      /* 480 */
#define ADJ_RPB 64
#define ADJ_BLOCKS (BBATCH*SSZ*SSZ/ADJ_RPB)   /* 9216 */

__global__ __launch_bounds__(128) void stage1(
    const float* __restrict__ adj, const float* __restrict__ X,
    const float* __restrict__ W0, const float* __restrict__ W1,
    const float* __restrict__ Wout, const float* __restrict__ bout)
{
    int bx = blockIdx.x;
    if (bx < ADJ_BLOCKS) {
        // ---- adj reduction: 64 rows/block, smem-staged (stream starts first)
        __shared__ float buf[ADJ_RPB][51];
        __shared__ float swe[EE];
        int tid = threadIdx.x;
        if (tid < EE) swe[tid] = g_we[tid];
        size_t r0 = (size_t)bx * ADJ_RPB;
        const float4* src = (const float4*)(adj + r0 * EE);
        for (int idx = tid; idx < ADJ_RPB*EE/4; idx += 128) {
            float4 v = src[idx];
            int g = idx * 4;
            buf[(g  )/EE][(g  )%EE] = v.x;
            buf[(g+1)/EE][(g+1)%EE] = v.y;
            buf[(g+2)/EE][(g+2)%EE] = v.z;
            buf[(g+3)/EE][(g+3)%EE] = v.w;
        }
        __syncthreads();
        if (tid < ADJ_RPB) {
            float s0 = 0.f, s1 = 0.f;
            #pragma unroll 10
            for (int e = 0; e < EE; e++) {
                float v = buf[tid][e];
                s0 += v;
                s1 = fmaf(v, swe[e], s1);
            }
            g_A0[r0 + tid] = s0;
            g_A1[r0 + tid] = s1;
        }
        return;
    }
    bx -= ADJ_BLOCKS;
    if (bx < QB) {               // Q = X @ W0^T
        ntB16<0>(X, DD, DD, nullptr, W0, DD, HH, (bx/5)*64, (bx%5)*32,
                 nullptr, nullptr, g_Q, HH);
        return;
    }
    if (bx < QB + PXB) {         // PX = X @ W1[:, :300]^T
        int t = bx - QB;
        ntB16<0>(X, DD, DD, nullptr, W1, D1, HH, (t/5)*64, (t%5)*32,
                 nullptr, nullptr, g_P, HH);
        return;
    }
    {                            // OX = X @ Wout^T + bout
        int t = bx - QB - PXB;
        ntB16<0>(X, DD, DD, nullptr, Wout, DD, DD, (t/10)*64, (t%10)*32,
                 bout, nullptr, g_OX, DD);
    }
}

// ======= bat: batched NN GEMM, split-K x2, whole-K smem, one sync ===========
// grid (5, 6, 8). Tile 64x32, K=192 per half. Dynamic smem SK=192.
#define BAT_SK 192
#define BAT_SMEM (BAT_SK*(68+36)*4)
template<int MODE>
__global__ __launch_bounds__(128) void bat() {
    extern __shared__ __align__(16) float dsm[];
    float (*As)[68] = (float(*)[68])dsm;
    float (*Bs)[36] = (float(*)[36])(dsm + BAT_SK*68);
    int zc = blockIdx.z;
    int b = zc >> 1, half = zc & 1;
    const float* A  = (MODE==0 ? g_A0 : g_A1) + (size_t)b * SSZ * SSZ;
    const float* Bm = (MODE==0 ? g_Q  : g_P ) + (size_t)b * SSZ * HH;
    float* Cp = (MODE==0) ? (half ? g_c0b : g_c0a) : (half ? g_c1b : g_c1a);
    int m0 = blockIdx.y * 64, n0 = blockIdx.x * 32;
    int tid = threadIdx.x;
    int arow = tid >> 1, aq = (tid & 1) * 4;
    int bk = tid >> 3, bn = (tid & 7) * 4;
    int tx = tid & 7, ty = tid >> 3;
    int kbase = half * 192;

    const float* Arow = A + (size_t)(m0 + arow) * SSZ + kbase;
    const float* s1p = g_s1 + b * SSZ + kbase;
    float s2i = 0.f;
    if (MODE == 1) s2i = g_s2[b*SSZ + m0 + arow] + g_sbh;

    // ---- load phase: 12 chunks, no syncs ----
    for (int it = 0; it < 12; it++) {
        int k0 = it * 16;
        float ar[8], br[4];
        #pragma unroll
        for (int h = 0; h < 2; h++) {
            int k = k0 + aq + h*8;
            float4 v = *(const float4*)(Arow + k);
            if (MODE == 1) {
                float4 s = *(const float4*)(s1p + k);
                v.x += s.x + s2i; v.y += s.y + s2i; v.z += s.z + s2i; v.w += s.w + s2i;
            }
            ar[h*4]=v.x; ar[h*4+1]=v.y; ar[h*4+2]=v.z; ar[h*4+3]=v.w;
        }
        {
            const float* p = Bm + (size_t)(kbase + k0 + bk) * HH + n0 + bn;
            #pragma unroll
            for (int t = 0; t < 2; t++) {
                int n = n0 + bn + 2*t;
                float2 v = (n < HH) ? *(const float2*)(p + 2*t) : make_float2(0.f,0.f);
                br[2*t] = v.x; br[2*t+1] = v.y;
            }
        }
        #pragma unroll
        for (int h = 0; h < 2; h++)
            #pragma unroll
            for (int j = 0; j < 4; j++)
                As[k0 + aq + h*8 + j][arow] = ar[h*4 + j];
        #pragma unroll
        for (int j = 0; j < 4; j++) Bs[k0 + bk][bn + j] = br[j];
    }
    __syncthreads();

    // ---- compute phase: 192 k-steps, zero syncs ----
    float acc[4][4] = {};
    for (int kk = 0; kk < 192; kk++) {
        float4 a = *(const float4*)&As[kk][ty*4];
        float4 w = *(const float4*)&Bs[kk][tx*4];
        float am[4] = {a.x,a.y,a.z,a.w};
        float wm[4] = {w.x,w.y,w.z,w.w};
        #pragma unroll
        for (int i = 0; i < 4; i++)
            #pragma unroll
            for (int j = 0; j < 4; j++)
                acc[i][j] = fmaf(am[i], wm[j], acc[i][j]);
    }

    #pragma unroll
    for (int i = 0; i < 4; i++) {
        int row = b*SSZ + m0 + ty*4 + i;
        #pragma unroll
        for (int j = 0; j < 4; j++) {
            int n = n0 + tx*4 + j;
            if (n < HH) Cp[(size_t)row*HH + n] = acc[i][j];
        }
    }
}

// ======= stage3: P += g0@W1b^T ; OX += g0@WoutA^T ; s1/s2 ===================
#define PAB 120
#define OAB 240
#define ST3_SK 160
#define ST3_SMEM (ST3_SK*(68+36)*4)
__global__ __launch_bounds__(128) void stage3(const float* __restrict__ W1,
                                              const float* __restrict__ Wout,
                                              const float* __restrict__ b0) {
    int bx = blockIdx.x;
    if (bx < PAB) {
        ntBig<1, ST3_SK>(nullptr, 0, HH, b0, W1 + DD, D1, HH, (bx/5)*64, (bx%5)*32,
                         nullptr, g_P, g_P, HH);
        return;
    }
    if (bx < PAB + OAB) {
        int t = bx - PAB;
        ntBig<1, ST3_SK>(nullptr, 0, HH, b0, Wout, DD, DD, (t/10)*64, (t%10)*32,
                         nullptr, g_OX, g_OX, DD);
        return;
    }
    // s1/s2: thread per row of g0 (recompute epilogue on load)
    __shared__ float sw1[HH], sw2[HH], sb0[HH];
    int tid = threadIdx.x;
    for (int i = tid; i < HH; i += 128) {
        sw1[i] = g_w1s[i]; sw2[i] = g_w2s[i]; sb0[i] = b0[i];
    }
    __syncthreads();
    int row = (bx - PAB - OAB) * 128 + tid;
    const float* pa = g_c0a + (size_t)row * HH;
    const float* pb = g_c0b + (size_t)row * HH;
    const float* pq = g_Q   + (size_t)row * HH;
    float a1 = 0.f, a2 = 0.f;
    for (int k = 0; k < HH; k += 2) {
        float2 a = *(const float2*)(pa + k);
        float2 b = *(const float2*)(pb + k);
        float2 q = *(const float2*)(pq + k);
        float gx = fmaxf(fmaf(a.x + b.x, INVE, q.x + 2.f*sb0[k]),   0.f);
        float gy = fmaxf(fmaf(a.y + b.y, INVE, q.y + 2.f*sb0[k+1]), 0.f);
        a1 = fmaf(gx, sw1[k], a1);  a1 = fmaf(gy, sw1[k+1], a1);
        a2 = fmaf(gx, sw2[k], a2);  a2 = fmaf(gy, sw2[k+1], a2);
    }
    g_s1[row] = a1;
    g_s2[row] = a2;
}

// ======= stage6: out = OX + g1@WoutB^T ======================================
#define OXT 240
__global__ __launch_bounds__(128) void stage6(const float* __restrict__ Wout,
                                              const float* __restrict__ b1,
                                              float* __restrict__ out) {
    int bx = blockIdx.x;
    ntBig<2, ST3_SK>(nullptr, 0, HH, b1, Wout + HH, DD, DD, (bx/10)*64, (bx%10)*32,
                     nullptr, g_OX, out, DD);
}

// ======= launch =============================================================
extern "C" void kernel_launch(void* const* d_in, const int* in_sizes, int n_in,
                              void* d_out, int out_size) {
    const float* adj  = (const float*)d_in[0];
    const float* X    = (const float*)d_in[1];
    const float* W0   = (const float*)d_in[2];
    const float* b0   = (const float*)d_in[3];
    const float* W1   = (const float*)d_in[4];
    const float* b1   = (const float*)d_in[5];
    const float* Wh   = (const float*)d_in[6];
    const float* bh   = (const float*)d_in[7];
    const float* Wout = (const float*)d_in[8];
    const float* bout = (const float*)d_in[9];
    float* out = (float*)d_out;

    static int attr_done = 0;
    cudaFuncSetAttribute(bat<0>,  cudaFuncAttributeMaxDynamicSharedMemorySize, BAT_SMEM);
    cudaFuncSetAttribute(bat<1>,  cudaFuncAttributeMaxDynamicSharedMemorySize, BAT_SMEM);
    cudaFuncSetAttribute(stage3,  cudaFuncAttributeMaxDynamicSharedMemorySize, ST3_SMEM);
    cudaFuncSetAttribute(stage6,  cudaFuncAttributeMaxDynamicSharedMemorySize, ST3_SMEM);
    (void)attr_done;

    prep_weights<<<1, 256>>>(Wh, bh);

    // adj stream (first) + Q, PX, OX GEMMs in one launch
    stage1<<<ADJ_BLOCKS + GEMMB, 128>>>(adj, X, W0, W1, Wout, bout);

    // split-K partials of A0@Q  (whole-K smem core)
    bat<0><<<dim3(5, 6, 8), 128, BAT_SMEM>>>();

    // P += g0@W1b^T ; OX += g0@WoutA^T ; s1/s2
    stage3<<<PAB + OAB + 12, 128, ST3_SMEM>>>(W1, Wout, b0);

    // split-K partials of Atilde1@P
    bat<1><<<dim3(5, 6, 8), 128, BAT_SMEM>>>();

    // out = OX + g1@WoutB^T
    stage6<<<OXT, 128, ST3_SMEM>>>(Wout, b1, out);
}

// round 15
// speedup vs baseline: 1.5272x; 1.5272x over previous
#include <cuda_runtime.h>
#include <cstdint>

#define BBATCH 4
#define SSZ 384
#define DD 300
#define EE 50
#define HH 150
#define BSR (BBATCH*SSZ)   /* 1536 */
#define D1 450
#define INVE (1.0f/50.0f)

// ---------------- device scratch ----------------
__device__ float g_we[EE];
__device__ float g_w1s[HH];
__device__ float g_w2s[HH];
__device__ float g_sbh;
__device__ float g_A0[BBATCH*SSZ*SSZ];
__device__ float g_A1[BBATCH*SSZ*SSZ];
__device__ float g_Q [BSR*HH];
__device__ float g_P [BSR*HH];
__device__ float g_OX[BSR*DD];
__device__ float g_s1[BSR];
__device__ float g_s2[BSR];
__device__ float g_c0a[BSR*HH];   // bat0 split-K partials
__device__ float g_c0b[BSR*HH];
__device__ float g_c1a[BSR*HH];   // bat1 split-K partials
__device__ float g_c1b[BSR*HH];

// ---------------- prep ------------------------------------------------------
__global__ void prep_weights(const float* __restrict__ Wh, const float* __restrict__ bh) {
    int t = threadIdx.x;
    const int WHC = 2*HH + EE;
    if (t < EE) {
        float s = 0.f;
        for (int f = 0; f < EE; f++) s += Wh[f*WHC + t];
        g_we[t] = s;
    }
    if (t < HH) {
        float a = 0.f, b = 0.f;
        for (int f = 0; f < EE; f++) {
            a += Wh[f*WHC + EE + t];
            b += Wh[f*WHC + EE + HH + t];
        }
        g_w1s[t] = a;
        g_w2s[t] = b;
    }
    if (t == 0) {
        float s = 0.f;
        for (int e = 0; e < EE; e++) s += bh[e];
        g_sbh = s;
    }
}

// ---- A-operand loaders (round-5 proven): 8 k-values {kq..kq+3, kq+8..kq+11} -
// ASRC 0: raw fp32 ; ASRC 1: g0 epilogue ; ASRC 2: g1 epilogue
template<int ASRC>
__device__ __forceinline__ void ldA8(float* ar, const float* __restrict__ A, int lda,
                                     const float* __restrict__ ba,
                                     int m, int kq, int K) {
    if (ASRC == 0) {
        const float* p = A + (size_t)m * lda;
        #pragma unroll
        for (int h = 0; h < 2; h++) {
            int k = kq + h*8;
            float4 v = (k < K) ? *(const float4*)(p + k) : make_float4(0.f,0.f,0.f,0.f);
            ar[h*4+0]=v.x; ar[h*4+1]=v.y; ar[h*4+2]=v.z; ar[h*4+3]=v.w;
        }
    } else {
        const float* pa = (ASRC==1) ? g_c0a : g_c1a;
        const float* pb = (ASRC==1) ? g_c0b : g_c1b;
        const float* pq = (ASRC==1) ? g_Q   : g_P;
        size_t base = (size_t)m * HH;
        #pragma unroll
        for (int h = 0; h < 2; h++) {
            #pragma unroll
            for (int t = 0; t < 2; t++) {
                int k = kq + h*8 + t*2;
                float rx = 0.f, ry = 0.f;
                if (k < K) {
                    float2 a = *(const float2*)(pa + base + k);
                    float2 b = *(const float2*)(pb + base + k);
                    float2 q = *(const float2*)(pq + base + k);
                    float2 bb = *(const float2*)(ba + k);
                    rx = fmaxf(fmaf(a.x + b.x, INVE, q.x + 2.f*bb.x), 0.f);
                    ry = fmaxf(fmaf(a.y + b.y, INVE, q.y + 2.f*bb.y), 0.f);
                }
                ar[h*4 + t*2] = rx; ar[h*4 + t*2 + 1] = ry;
            }
        }
    }
}

// ======= NT GEMM core: 64x32 tile, 128 thr, 4x4 micro (round-5 proven) ======
template<int ASRC>
__device__ __forceinline__ void ntB(
    const float* __restrict__ A, int lda, int K,
    const float* __restrict__ baA,
    const float* __restrict__ W, int ldw, int N,
    int m0, int n0,
    const float* __restrict__ biasC, const float* __restrict__ Cadd,
    float* __restrict__ C, int ldc)
{
    __shared__ __align__(16) float As[16][68];
    __shared__ __align__(16) float Ws[16][36];
    int tid = threadIdx.x;
    int arow = tid >> 1, aq = (tid & 1) * 4;
    int wrow = tid >> 2, wq = (tid & 3) * 2;
    int tx = tid & 7, ty = tid >> 3;
    int NIT = (K + 15) >> 4;

    int mA = m0 + arow;
    int nW = n0 + wrow;
    bool nok = nW < N;
    const float* Wrow = W + (size_t)(nok ? nW : 0) * ldw;

    float ar[8], wr[4];
    float acc[4][4] = {};

    ldA8<ASRC>(ar, A, lda, baA, mA, aq, K);
    #pragma unroll
    for (int h = 0; h < 2; h++) {
        int k = wq + h*8;
        float2 v = (nok && k < K) ? *(const float2*)(Wrow + k) : make_float2(0.f,0.f);
        wr[h*2] = v.x; wr[h*2+1] = v.y;
    }

    for (int it = 0; it < NIT; it++) {
        __syncthreads();
        #pragma unroll
        for (int h = 0; h < 2; h++)
            #pragma unroll
            for (int j = 0; j < 4; j++)
                As[aq + h*8 + j][arow] = ar[h*4 + j];
        #pragma unroll
        for (int h = 0; h < 2; h++)
            #pragma unroll
            for (int j = 0; j < 2; j++)
                Ws[wq + h*8 + j][wrow] = wr[h*2 + j];
        __syncthreads();
        if (it + 1 < NIT) {
            int k0 = (it + 1) * 16;
            ldA8<ASRC>(ar, A, lda, baA, mA, k0 + aq, K);
            #pragma unroll
            for (int h = 0; h < 2; h++) {
                int k = k0 + wq + h*8;
                float2 v = (nok && k < K) ? *(const float2*)(Wrow + k) : make_float2(0.f,0.f);
                wr[h*2] = v.x; wr[h*2+1] = v.y;
            }
        }
        #pragma unroll
        for (int kk = 0; kk < 16; kk++) {
            float4 a = *(const float4*)&As[kk][ty*4];
            float4 w = *(const float4*)&Ws[kk][tx*4];
            float am[4] = {a.x,a.y,a.z,a.w};
            float wm[4] = {w.x,w.y,w.z,w.w};
            #pragma unroll
            for (int i = 0; i < 4; i++)
                #pragma unroll
                for (int j = 0; j < 4; j++)
                    acc[i][j] = fmaf(am[i], wm[j], acc[i][j]);
        }
    }

    #pragma unroll
    for (int i = 0; i < 4; i++) {
        int m = m0 + ty*4 + i;
        #pragma unroll
        for (int j = 0; j < 4; j++) {
            int n = n0 + tx*4 + j;
            if (n < N) {
                float v = acc[i][j];
                if (biasC) v += biasC[n];
                if (Cadd) v += Cadd[(size_t)m*ldc + n];
                C[(size_t)m*ldc + n] = v;
            }
        }
    }
}

// ======= stage1: adj reduction FIRST, then Q, PX, OX GEMMs ==================
#define QB 120
#define PXB 120
#define OXB 240
#define GEMMB (QB+PXB+OXB)      /* 480 */
#define ADJ_RPB 128
#define ADJ_BLOCKS (BBATCH*SSZ*SSZ/ADJ_RPB)   /* 4608 */

__global__ __launch_bounds__(128) void stage1(
    const float* __restrict__ adj, const float* __restrict__ X,
    const float* __restrict__ W0, const float* __restrict__ W1,
    const float* __restrict__ Wout, const float* __restrict__ bout)
{
    int bx = blockIdx.x;
    if (bx < ADJ_BLOCKS) {
        // ---- adj reduction: 128 rows/block, smem-staged ----
        __shared__ float buf[ADJ_RPB][51];
        __shared__ float swe[EE];
        int tid = threadIdx.x;
        if (tid < EE) swe[tid] = g_we[tid];
        size_t r0 = (size_t)bx * ADJ_RPB;
        const float4* src = (const float4*)(adj + r0 * EE);
        for (int idx = tid; idx < ADJ_RPB*EE/4; idx += 128) {
            float4 v = src[idx];
            int g = idx * 4;
            buf[(g  )/EE][(g  )%EE] = v.x;
            buf[(g+1)/EE][(g+1)%EE] = v.y;
            buf[(g+2)/EE][(g+2)%EE] = v.z;
            buf[(g+3)/EE][(g+3)%EE] = v.w;
        }
        __syncthreads();
        {
            float s0 = 0.f, s1 = 0.f;
            #pragma unroll 10
            for (int e = 0; e < EE; e++) {
                float v = buf[tid][e];
                s0 += v;
                s1 = fmaf(v, swe[e], s1);
            }
            g_A0[r0 + tid] = s0;
            g_A1[r0 + tid] = s1;
        }
        return;
    }
    bx -= ADJ_BLOCKS;
    if (bx < QB) {               // Q = X @ W0^T
        ntB<0>(X, DD, DD, nullptr, W0, DD, HH, (bx/5)*64, (bx%5)*32,
               nullptr, nullptr, g_Q, HH);
        return;
    }
    if (bx < QB + PXB) {         // PX = X @ W1[:, :300]^T
        int t = bx - QB;
        ntB<0>(X, DD, DD, nullptr, W1, D1, HH, (t/5)*64, (t%5)*32,
               nullptr, nullptr, g_P, HH);
        return;
    }
    {                            // OX = X @ Wout^T + bout
        int t = bx - QB - PXB;
        ntB<0>(X, DD, DD, nullptr, Wout, DD, DD, (t/10)*64, (t%10)*32,
               bout, nullptr, g_OX, DD);
    }
}

// ======= bat: batched NN GEMM, split-K x2, 64x32 tile (round-5 proven) ======
// MODE 0: partial of A0@Q ; MODE 1: partial of Atilde1@P (rank-2 fold in A)
template<int MODE>
__global__ __launch_bounds__(128) void bat() {
    __shared__ __align__(16) float As[16][68];
    __shared__ __align__(8)  float Bs[16][34];
    int zc = blockIdx.z;
    int b = zc >> 1, half = zc & 1;
    const float* A  = (MODE==0 ? g_A0 : g_A1) + (size_t)b * SSZ * SSZ;
    const float* Bm = (MODE==0 ? g_Q  : g_P ) + (size_t)b * SSZ * HH;
    float* Cp = (MODE==0) ? (half ? g_c0b : g_c0a) : (half ? g_c1b : g_c1a);
    int m0 = blockIdx.y * 64, n0 = blockIdx.x * 32;
    int tid = threadIdx.x;
    int arow = tid >> 1, aq = (tid & 1) * 4;
    int bk = tid >> 3, bn = (tid & 7) * 4;
    int tx = tid & 7, ty = tid >> 3;
    int kbase = half * 192;

    const float* Arow = A + (size_t)(m0 + arow) * SSZ + kbase;
    const float* s1p = g_s1 + b * SSZ + kbase;
    float s2i = 0.f;
    if (MODE == 1) s2i = g_s2[b*SSZ + m0 + arow] + g_sbh;

    float ar[8], br[4];
    float acc[4][4] = {};

    // prefetch it=0
    #pragma unroll
    for (int h = 0; h < 2; h++) {
        int k = aq + h*8;
        float4 v = *(const float4*)(Arow + k);
        if (MODE == 1) {
            float4 s = *(const float4*)(s1p + k);
            v.x += s.x + s2i; v.y += s.y + s2i; v.z += s.z + s2i; v.w += s.w + s2i;
        }
        ar[h*4]=v.x; ar[h*4+1]=v.y; ar[h*4+2]=v.z; ar[h*4+3]=v.w;
    }
    {
        const float* p = Bm + (size_t)(kbase + bk) * HH + n0 + bn;
        #pragma unroll
        for (int t = 0; t < 2; t++) {
            int n = n0 + bn + 2*t;
            float2 v = (n < HH) ? *(const float2*)(p + 2*t) : make_float2(0.f,0.f);
            br[2*t] = v.x; br[2*t+1] = v.y;
        }
    }

    for (int it = 0; it < 12; it++) {
        __syncthreads();
        #pragma unroll
        for (int h = 0; h < 2; h++)
            #pragma unroll
            for (int j = 0; j < 4; j++)
                As[aq + h*8 + j][arow] = ar[h*4 + j];
        #pragma unroll
        for (int j = 0; j < 4; j++) Bs[bk][bn + j] = br[j];
        __syncthreads();
        if (it + 1 < 12) {
            int k0 = (it + 1) * 16;
            #pragma unroll
            for (int h = 0; h < 2; h++) {
                int k = k0 + aq + h*8;
                float4 v = *(const float4*)(Arow + k);
                if (MODE == 1) {
                    float4 s = *(const float4*)(s1p + k);
                    v.x += s.x + s2i; v.y += s.y + s2i; v.z += s.z + s2i; v.w += s.w + s2i;
                }
                ar[h*4]=v.x; ar[h*4+1]=v.y; ar[h*4+2]=v.z; ar[h*4+3]=v.w;
            }
            const float* p = Bm + (size_t)(kbase + k0 + bk) * HH + n0 + bn;
            #pragma unroll
            for (int t = 0; t < 2; t++) {
                int n = n0 + bn + 2*t;
                float2 v = (n < HH) ? *(const float2*)(p + 2*t) : make_float2(0.f,0.f);
                br[2*t] = v.x; br[2*t+1] = v.y;
            }
        }
        #pragma unroll
        for (int kk = 0; kk < 16; kk++) {
            float4 a = *(const float4*)&As[kk][ty*4];
            float2 b0v = *(const float2*)&Bs[kk][tx*4];
            float2 b1v = *(const float2*)&Bs[kk][tx*4 + 2];
            float am[4] = {a.x,a.y,a.z,a.w};
            float wm[4] = {b0v.x,b0v.y,b1v.x,b1v.y};
            #pragma unroll
            for (int i = 0; i < 4; i++)
                #pragma unroll
                for (int j = 0; j < 4; j++)
                    acc[i][j] = fmaf(am[i], wm[j], acc[i][j]);
        }
    }

    #pragma unroll
    for (int i = 0; i < 4; i++) {
        int row = b*SSZ + m0 + ty*4 + i;
        #pragma unroll
        for (int j = 0; j < 4; j++) {
            int n = n0 + tx*4 + j;
            if (n < HH) Cp[(size_t)row*HH + n] = acc[i][j];
        }
    }
}

// ======= stage3: P += g0@W1b^T ; OX += g0@WoutA^T ; s1/s2 ===================
#define PAB 120
#define OAB 240
__global__ __launch_bounds__(128) void stage3(const float* __restrict__ W1,
                                              const float* __restrict__ Wout,
                                              const float* __restrict__ b0) {
    int bx = blockIdx.x;
    if (bx < PAB) {
        ntB<1>(nullptr, 0, HH, b0, W1 + DD, D1, HH, (bx/5)*64, (bx%5)*32,
               nullptr, g_P, g_P, HH);
        return;
    }
    if (bx < PAB + OAB) {
        int t = bx - PAB;
        ntB<1>(nullptr, 0, HH, b0, Wout, DD, DD, (t/10)*64, (t%10)*32,
               nullptr, g_OX, g_OX, DD);
        return;
    }
    // s1/s2: thread per row of g0 (recompute epilogue on load)
    __shared__ float sw1[HH], sw2[HH], sb0[HH];
    int tid = threadIdx.x;
    for (int i = tid; i < HH; i += 128) {
        sw1[i] = g_w1s[i]; sw2[i] = g_w2s[i]; sb0[i] = b0[i];
    }
    __syncthreads();
    int row = (bx - PAB - OAB) * 128 + tid;
    const float* pa = g_c0a + (size_t)row * HH;
    const float* pb = g_c0b + (size_t)row * HH;
    const float* pq = g_Q   + (size_t)row * HH;
    float a1 = 0.f, a2 = 0.f;
    for (int k = 0; k < HH; k += 2) {
        float2 a = *(const float2*)(pa + k);
        float2 b = *(const float2*)(pb + k);
        float2 q = *(const float2*)(pq + k);
        float gx = fmaxf(fmaf(a.x + b.x, INVE, q.x + 2.f*sb0[k]),   0.f);
        float gy = fmaxf(fmaf(a.y + b.y, INVE, q.y + 2.f*sb0[k+1]), 0.f);
        a1 = fmaf(gx, sw1[k], a1);  a1 = fmaf(gy, sw1[k+1], a1);
        a2 = fmaf(gx, sw2[k], a2);  a2 = fmaf(gy, sw2[k+1], a2);
    }
    g_s1[row] = a1;
    g_s2[row] = a2;
}

// ======= stage6: out = OX + g1@WoutB^T ======================================
#define OXT 240
__global__ __launch_bounds__(128) void stage6(const float* __restrict__ Wout,
                                              const float* __restrict__ b1,
                                              float* __restrict__ out) {
    int bx = blockIdx.x;
    ntB<2>(nullptr, 0, HH, b1, Wout + HH, DD, DD, (bx/10)*64, (bx%10)*32,
           nullptr, g_OX, out, DD);
}

// ======= launch =============================================================
extern "C" void kernel_launch(void* const* d_in, const int* in_sizes, int n_in,
                              void* d_out, int out_size) {
    const float* adj  = (const float*)d_in[0];
    const float* X    = (const float*)d_in[1];
    const float* W0   = (const float*)d_in[2];
    const float* b0   = (const float*)d_in[3];
    const float* W1   = (const float*)d_in[4];
    const float* b1   = (const float*)d_in[5];
    const float* Wh   = (const float*)d_in[6];
    const float* bh   = (const float*)d_in[7];
    const float* Wout = (const float*)d_in[8];
    const float* bout = (const float*)d_in[9];
    float* out = (float*)d_out;

    prep_weights<<<1, 256>>>(Wh, bh);

    // adj stream first (HBM read starts immediately) + Q, PX, OX GEMMs behind it
    stage1<<<ADJ_BLOCKS + GEMMB, 128>>>(adj, X, W0, W1, Wout, bout);

    // split-K partials of A0@Q
    bat<0><<<dim3(5, 6, 8), 128>>>();

    // P += g0@W1b^T ; OX += g0@WoutA^T ; s1/s2  (g0 epilogue fused in loads)
    stage3<<<PAB + OAB + 12, 128>>>(W1, Wout, b0);

    // split-K partials of Atilde1@P  (rank-2 correction folded into A)
    bat<1><<<dim3(5, 6, 8), 128>>>();

    // out = OX + g1@WoutB^T   (g1 epilogue fused in loads)
    stage6<<<OXT, 128>>>(Wout, b1, out);
}

// round 16
// speedup vs baseline: 1.5344x; 1.0047x over previous
#include <cuda_runtime.h>
#include <cstdint>

#define BBATCH 4
#define SSZ 384
#define DD 300
#define EE 50
#define HH 150
#define BSR (BBATCH*SSZ)   /* 1536 */
#define D1 450
#define INVE (1.0f/50.0f)

// ---------------- device scratch ----------------
__device__ float g_we[EE];
__device__ float g_w1s[HH];
__device__ float g_w2s[HH];
__device__ float g_sbh;
__device__ float g_A0[BBATCH*SSZ*SSZ];
__device__ float g_A1[BBATCH*SSZ*SSZ];
__device__ float g_Q [BSR*HH];
__device__ float g_P [BSR*HH];
__device__ float g_OX[BSR*DD];
__device__ float g_s1[BSR];
__device__ float g_s2[BSR];
__device__ float g_c0a[BSR*HH];   // bat0 split-K x4 partials
__device__ float g_c0b[BSR*HH];
__device__ float g_c0c[BSR*HH];
__device__ float g_c0d[BSR*HH];
__device__ float g_c1a[BSR*HH];   // bat1 split-K x4 partials
__device__ float g_c1b[BSR*HH];
__device__ float g_c1c[BSR*HH];
__device__ float g_c1d[BSR*HH];

// ---------------- prep ------------------------------------------------------
__global__ void prep_weights(const float* __restrict__ Wh, const float* __restrict__ bh) {
    int t = threadIdx.x;
    const int WHC = 2*HH + EE;
    if (t < EE) {
        float s = 0.f;
        for (int f = 0; f < EE; f++) s += Wh[f*WHC + t];
        g_we[t] = s;
    }
    if (t < HH) {
        float a = 0.f, b = 0.f;
        for (int f = 0; f < EE; f++) {
            a += Wh[f*WHC + EE + t];
            b += Wh[f*WHC + EE + HH + t];
        }
        g_w1s[t] = a;
        g_w2s[t] = b;
    }
    if (t == 0) {
        float s = 0.f;
        for (int e = 0; e < EE; e++) s += bh[e];
        g_sbh = s;
    }
}

// ---- A-operand loaders: 8 k-values {kq..kq+3, kq+8..kq+11} ------------------
// ASRC 0: raw fp32
// ASRC 1: g0 = relu((c0a+c0b+c0c+c0d)/E + Q + 2*b0)
// ASRC 2: g1 = relu((c1a+c1b+c1c+c1d)/E + P + 2*b1)
template<int ASRC>
__device__ __forceinline__ void ldA8(float* ar, const float* __restrict__ A, int lda,
                                     const float* __restrict__ ba,
                                     int m, int kq, int K) {
    if (ASRC == 0) {
        const float* p = A + (size_t)m * lda;
        #pragma unroll
        for (int h = 0; h < 2; h++) {
            int k = kq + h*8;
            float4 v = (k < K) ? *(const float4*)(p + k) : make_float4(0.f,0.f,0.f,0.f);
            ar[h*4+0]=v.x; ar[h*4+1]=v.y; ar[h*4+2]=v.z; ar[h*4+3]=v.w;
        }
    } else {
        const float* pa = (ASRC==1) ? g_c0a : g_c1a;
        const float* pb = (ASRC==1) ? g_c0b : g_c1b;
        const float* pc = (ASRC==1) ? g_c0c : g_c1c;
        const float* pd = (ASRC==1) ? g_c0d : g_c1d;
        const float* pq = (ASRC==1) ? g_Q   : g_P;
        size_t base = (size_t)m * HH;
        #pragma unroll
        for (int h = 0; h < 2; h++) {
            #pragma unroll
            for (int t = 0; t < 2; t++) {
                int k = kq + h*8 + t*2;
                float rx = 0.f, ry = 0.f;
                if (k < K) {
                    float2 a = *(const float2*)(pa + base + k);
                    float2 b = *(const float2*)(pb + base + k);
                    float2 c = *(const float2*)(pc + base + k);
                    float2 d = *(const float2*)(pd + base + k);
                    float2 q = *(const float2*)(pq + base + k);
                    float2 bb = *(const float2*)(ba + k);
                    rx = fmaxf(fmaf((a.x + b.x) + (c.x + d.x), INVE, q.x + 2.f*bb.x), 0.f);
                    ry = fmaxf(fmaf((a.y + b.y) + (c.y + d.y), INVE, q.y + 2.f*bb.y), 0.f);
                }
                ar[h*4 + t*2] = rx; ar[h*4 + t*2 + 1] = ry;
            }
        }
    }
}

// ======= NT GEMM core: 64x32 tile, 128 thr, 4x4 micro (round-5 proven) ======
template<int ASRC>
__device__ __forceinline__ void ntB(
    const float* __restrict__ A, int lda, int K,
    const float* __restrict__ baA,
    const float* __restrict__ W, int ldw, int N,
    int m0, int n0,
    const float* __restrict__ biasC, const float* __restrict__ Cadd,
    float* __restrict__ C, int ldc)
{
    __shared__ __align__(16) float As[16][68];
    __shared__ __align__(16) float Ws[16][36];
    int tid = threadIdx.x;
    int arow = tid >> 1, aq = (tid & 1) * 4;
    int wrow = tid >> 2, wq = (tid & 3) * 2;
    int tx = tid & 7, ty = tid >> 3;
    int NIT = (K + 15) >> 4;

    int mA = m0 + arow;
    int nW = n0 + wrow;
    bool nok = nW < N;
    const float* Wrow = W + (size_t)(nok ? nW : 0) * ldw;

    float ar[8], wr[4];
    float acc[4][4] = {};

    ldA8<ASRC>(ar, A, lda, baA, mA, aq, K);
    #pragma unroll
    for (int h = 0; h < 2; h++) {
        int k = wq + h*8;
        float2 v = (nok && k < K) ? *(const float2*)(Wrow + k) : make_float2(0.f,0.f);
        wr[h*2] = v.x; wr[h*2+1] = v.y;
    }

    for (int it = 0; it < NIT; it++) {
        __syncthreads();
        #pragma unroll
        for (int h = 0; h < 2; h++)
            #pragma unroll
            for (int j = 0; j < 4; j++)
                As[aq + h*8 + j][arow] = ar[h*4 + j];
        #pragma unroll
        for (int h = 0; h < 2; h++)
            #pragma unroll
            for (int j = 0; j < 2; j++)
                Ws[wq + h*8 + j][wrow] = wr[h*2 + j];
        __syncthreads();
        if (it + 1 < NIT) {
            int k0 = (it + 1) * 16;
            ldA8<ASRC>(ar, A, lda, baA, mA, k0 + aq, K);
            #pragma unroll
            for (int h = 0; h < 2; h++) {
                int k = k0 + wq + h*8;
                float2 v = (nok && k < K) ? *(const float2*)(Wrow + k) : make_float2(0.f,0.f);
                wr[h*2] = v.x; wr[h*2+1] = v.y;
            }
        }
        #pragma unroll
        for (int kk = 0; kk < 16; kk++) {
            float4 a = *(const float4*)&As[kk][ty*4];
            float4 w = *(const float4*)&Ws[kk][tx*4];
            float am[4] = {a.x,a.y,a.z,a.w};
            float wm[4] = {w.x,w.y,w.z,w.w};
            #pragma unroll
            for (int i = 0; i < 4; i++)
                #pragma unroll
                for (int j = 0; j < 4; j++)
                    acc[i][j] = fmaf(am[i], wm[j], acc[i][j]);
        }
    }

    #pragma unroll
    for (int i = 0; i < 4; i++) {
        int m = m0 + ty*4 + i;
        #pragma unroll
        for (int j = 0; j < 4; j++) {
            int n = n0 + tx*4 + j;
            if (n < N) {
                float v = acc[i][j];
                if (biasC) v += biasC[n];
                if (Cadd) v += Cadd[(size_t)m*ldc + n];
                C[(size_t)m*ldc + n] = v;
            }
        }
    }
}

// ======= stage1: Q, PX, OX GEMMs first, then adj reduction (round-5 order) ==
#define QB 120
#define PXB 120
#define OXB 240
#define GEMMB (QB+PXB+OXB)      /* 480 */
#define ADJ_RPB 64
#define ADJ_BLOCKS (BBATCH*SSZ*SSZ/ADJ_RPB)   /* 9216 */

__global__ __launch_bounds__(128) void stage1(
    const float* __restrict__ adj, const float* __restrict__ X,
    const float* __restrict__ W0, const float* __restrict__ W1,
    const float* __restrict__ Wout, const float* __restrict__ bout)
{
    int bx = blockIdx.x;
    if (bx < QB) {               // Q = X @ W0^T
        ntB<0>(X, DD, DD, nullptr, W0, DD, HH, (bx/5)*64, (bx%5)*32,
               nullptr, nullptr, g_Q, HH);
        return;
    }
    if (bx < QB + PXB) {         // PX = X @ W1[:, :300]^T
        int t = bx - QB;
        ntB<0>(X, DD, DD, nullptr, W1, D1, HH, (t/5)*64, (t%5)*32,
               nullptr, nullptr, g_P, HH);
        return;
    }
    if (bx < GEMMB) {            // OX = X @ Wout^T + bout
        int t = bx - QB - PXB;
        ntB<0>(X, DD, DD, nullptr, Wout, DD, DD, (t/10)*64, (t%10)*32,
               bout, nullptr, g_OX, DD);
        return;
    }
    // ---- adj reduction: 64 rows/block, smem-staged ----
    __shared__ float buf[ADJ_RPB][51];
    __shared__ float swe[EE];
    int tid = threadIdx.x;
    if (tid < EE) swe[tid] = g_we[tid];
    size_t r0 = (size_t)(bx - GEMMB) * ADJ_RPB;
    const float4* src = (const float4*)(adj + r0 * EE);
    for (int idx = tid; idx < ADJ_RPB*EE/4; idx += 128) {
        float4 v = src[idx];
        int g = idx * 4;
        buf[(g  )/EE][(g  )%EE] = v.x;
        buf[(g+1)/EE][(g+1)%EE] = v.y;
        buf[(g+2)/EE][(g+2)%EE] = v.z;
        buf[(g+3)/EE][(g+3)%EE] = v.w;
    }
    __syncthreads();
    if (tid < ADJ_RPB) {
        float s0 = 0.f, s1 = 0.f;
        #pragma unroll 10
        for (int e = 0; e < EE; e++) {
            float v = buf[tid][e];
            s0 += v;
            s1 = fmaf(v, swe[e], s1);
        }
        g_A0[r0 + tid] = s0;
        g_A1[r0 + tid] = s1;
    }
}

// ======= bat: batched NN GEMM, split-K x4, 64x32 tile =======================
// grid (5, 6, 16): z = b*4 + quarter, K = 96 per quarter (6 chunks of 16)
// MODE 0: partial of A0@Q ; MODE 1: partial of Atilde1@P (rank-2 fold in A)
template<int MODE>
__global__ __launch_bounds__(128) void bat() {
    __shared__ __align__(16) float As[16][68];
    __shared__ __align__(8)  float Bs[16][34];
    int zc = blockIdx.z;
    int b = zc >> 2, quarter = zc & 3;
    const float* A  = (MODE==0 ? g_A0 : g_A1) + (size_t)b * SSZ * SSZ;
    const float* Bm = (MODE==0 ? g_Q  : g_P ) + (size_t)b * SSZ * HH;
    float* Cp = (MODE==0)
        ? (quarter==0 ? g_c0a : quarter==1 ? g_c0b : quarter==2 ? g_c0c : g_c0d)
        : (quarter==0 ? g_c1a : quarter==1 ? g_c1b : quarter==2 ? g_c1c : g_c1d);
    int m0 = blockIdx.y * 64, n0 = blockIdx.x * 32;
    int tid = threadIdx.x;
    int arow = tid >> 1, aq = (tid & 1) * 4;
    int bk = tid >> 3, bn = (tid & 7) * 4;
    int tx = tid & 7, ty = tid >> 3;
    int kbase = quarter * 96;

    const float* Arow = A + (size_t)(m0 + arow) * SSZ + kbase;
    const float* s1p = g_s1 + b * SSZ + kbase;
    float s2i = 0.f;
    if (MODE == 1) s2i = g_s2[b*SSZ + m0 + arow] + g_sbh;

    float ar[8], br[4];
    float acc[4][4] = {};

    // prefetch it=0
    #pragma unroll
    for (int h = 0; h < 2; h++) {
        int k = aq + h*8;
        float4 v = *(const float4*)(Arow + k);
        if (MODE == 1) {
            float4 s = *(const float4*)(s1p + k);
            v.x += s.x + s2i; v.y += s.y + s2i; v.z += s.z + s2i; v.w += s.w + s2i;
        }
        ar[h*4]=v.x; ar[h*4+1]=v.y; ar[h*4+2]=v.z; ar[h*4+3]=v.w;
    }
    {
        const float* p = Bm + (size_t)(kbase + bk) * HH + n0 + bn;
        #pragma unroll
        for (int t = 0; t < 2; t++) {
            int n = n0 + bn + 2*t;
            float2 v = (n < HH) ? *(const float2*)(p + 2*t) : make_float2(0.f,0.f);
            br[2*t] = v.x; br[2*t+1] = v.y;
        }
    }

    for (int it = 0; it < 6; it++) {
        __syncthreads();
        #pragma unroll
        for (int h = 0; h < 2; h++)
            #pragma unroll
            for (int j = 0; j < 4; j++)
                As[aq + h*8 + j][arow] = ar[h*4 + j];
        #pragma unroll
        for (int j = 0; j < 4; j++) Bs[bk][bn + j] = br[j];
        __syncthreads();
        if (it + 1 < 6) {
            int k0 = (it + 1) * 16;
            #pragma unroll
            for (int h = 0; h < 2; h++) {
                int k = k0 + aq + h*8;
                float4 v = *(const float4*)(Arow + k);
                if (MODE == 1) {
                    float4 s = *(const float4*)(s1p + k);
                    v.x += s.x + s2i; v.y += s.y + s2i; v.z += s.z + s2i; v.w += s.w + s2i;
                }
                ar[h*4]=v.x; ar[h*4+1]=v.y; ar[h*4+2]=v.z; ar[h*4+3]=v.w;
            }
            const float* p = Bm + (size_t)(kbase + k0 + bk) * HH + n0 + bn;
            #pragma unroll
            for (int t = 0; t < 2; t++) {
                int n = n0 + bn + 2*t;
                float2 v = (n < HH) ? *(const float2*)(p + 2*t) : make_float2(0.f,0.f);
                br[2*t] = v.x; br[2*t+1] = v.y;
            }
        }
        #pragma unroll
        for (int kk = 0; kk < 16; kk++) {
            float4 a = *(const float4*)&As[kk][ty*4];
            float2 b0v = *(const float2*)&Bs[kk][tx*4];
            float2 b1v = *(const float2*)&Bs[kk][tx*4 + 2];
            float am[4] = {a.x,a.y,a.z,a.w};
            float wm[4] = {b0v.x,b0v.y,b1v.x,b1v.y};
            #pragma unroll
            for (int i = 0; i < 4; i++)
                #pragma unroll
                for (int j = 0; j < 4; j++)
                    acc[i][j] = fmaf(am[i], wm[j], acc[i][j]);
        }
    }

    #pragma unroll
    for (int i = 0; i < 4; i++) {
        int row = b*SSZ + m0 + ty*4 + i;
        #pragma unroll
        for (int j = 0; j < 4; j++) {
            int n = n0 + tx*4 + j;
            if (n < HH) Cp[(size_t)row*HH + n] = acc[i][j];
        }
    }
}

// ======= stage3: P += g0@W1b^T ; OX += g0@WoutA^T ; s1/s2 ===================
#define PAB 120
#define OAB 240
__global__ __launch_bounds__(128) void stage3(const float* __restrict__ W1,
                                              const float* __restrict__ Wout,
                                              const float* __restrict__ b0) {
    int bx = blockIdx.x;
    if (bx < PAB) {
        ntB<1>(nullptr, 0, HH, b0, W1 + DD, D1, HH, (bx/5)*64, (bx%5)*32,
               nullptr, g_P, g_P, HH);
        return;
    }
    if (bx < PAB + OAB) {
        int t = bx - PAB;
        ntB<1>(nullptr, 0, HH, b0, Wout, DD, DD, (t/10)*64, (t%10)*32,
               nullptr, g_OX, g_OX, DD);
        return;
    }
    // s1/s2: thread per row of g0 (recompute epilogue on load, 4 partials)
    __shared__ float sw1[HH], sw2[HH], sb0[HH];
    int tid = threadIdx.x;
    for (int i = tid; i < HH; i += 128) {
        sw1[i] = g_w1s[i]; sw2[i] = g_w2s[i]; sb0[i] = b0[i];
    }
    __syncthreads();
    int row = (bx - PAB - OAB) * 128 + tid;
    const float* pa = g_c0a + (size_t)row * HH;
    const float* pb = g_c0b + (size_t)row * HH;
    const float* pc = g_c0c + (size_t)row * HH;
    const float* pd = g_c0d + (size_t)row * HH;
    const float* pq = g_Q   + (size_t)row * HH;
    float a1 = 0.f, a2 = 0.f;
    for (int k = 0; k < HH; k += 2) {
        float2 a = *(const float2*)(pa + k);
        float2 b = *(const float2*)(pb + k);
        float2 c = *(const float2*)(pc + k);
        float2 d = *(const float2*)(pd + k);
        float2 q = *(const float2*)(pq + k);
        float gx = fmaxf(fmaf((a.x + b.x) + (c.x + d.x), INVE, q.x + 2.f*sb0[k]),   0.f);
        float gy = fmaxf(fmaf((a.y + b.y) + (c.y + d.y), INVE, q.y + 2.f*sb0[k+1]), 0.f);
        a1 = fmaf(gx, sw1[k], a1);  a1 = fmaf(gy, sw1[k+1], a1);
        a2 = fmaf(gx, sw2[k], a2);  a2 = fmaf(gy, sw2[k+1], a2);
    }
    g_s1[row] = a1;
    g_s2[row] = a2;
}

// ======= stage6: out = OX + g1@WoutB^T ======================================
#define OXT 240
__global__ __launch_bounds__(128) void stage6(const float* __restrict__ Wout,
                                              const float* __restrict__ b1,
                                              float* __restrict__ out) {
    int bx = blockIdx.x;
    ntB<2>(nullptr, 0, HH, b1, Wout + HH, DD, DD, (bx/10)*64, (bx%10)*32,
           nullptr, g_OX, out, DD);
}

// ======= launch =============================================================
extern "C" void kernel_launch(void* const* d_in, const int* in_sizes, int n_in,
                              void* d_out, int out_size) {
    const float* adj  = (const float*)d_in[0];
    const float* X    = (const float*)d_in[1];
    const float* W0   = (const float*)d_in[2];
    const float* b0   = (const float*)d_in[3];
    const float* W1   = (const float*)d_in[4];
    const float* b1   = (const float*)d_in[5];
    const float* Wh   = (const float*)d_in[6];
    const float* bh   = (const float*)d_in[7];
    const float* Wout = (const float*)d_in[8];
    const float* bout = (const float*)d_in[9];
    float* out = (float*)d_out;

    prep_weights<<<1, 256>>>(Wh, bh);

    // Q, PX, OX GEMMs overlapped with the 118MB adj streaming pass (GEMMs first)
    stage1<<<GEMMB + ADJ_BLOCKS, 128>>>(adj, X, W0, W1, Wout, bout);

    // split-K x4 partials of A0@Q
    bat<0><<<dim3(5, 6, 16), 128>>>();

    // P += g0@W1b^T ; OX += g0@WoutA^T ; s1/s2  (g0 epilogue fused in loads)
    stage3<<<PAB + OAB + 12, 128>>>(W1, Wout, b0);

    // split-K x4 partials of Atilde1@P  (rank-2 correction folded into A)
    bat<1><<<dim3(5, 6, 16), 128>>>();

    // out = OX + g1@WoutB^T   (g1 epilogue fused in loads)
    stage6<<<OXT, 128>>>(Wout, b1, out);
}

// round 17
// speedup vs baseline: 1.8699x; 1.2186x over previous
#include <cuda_runtime.h>
#include <cstdint>

#define BBATCH 4
#define SSZ 384
#define DD 300
#define EE 50
#define HH 150
#define BSR (BBATCH*SSZ)   /* 1536 */
#define D1 450
#define INVE (1.0f/50.0f)

// ---------------- device scratch ----------------
__device__ float g_we[EE];
__device__ float g_w1s[HH];
__device__ float g_w2s[HH];
__device__ float g_sbh;
__device__ float g_A0[BBATCH*SSZ*SSZ];
__device__ float g_A1[BBATCH*SSZ*SSZ];
__device__ float g_Q [BSR*HH];
__device__ float g_P [BSR*HH];
__device__ float g_OX[BSR*DD];
__device__ float g_s1[BSR];
__device__ float g_s2[BSR];
__device__ float g_g0[BSR*HH];    // materialized relu activations
__device__ float g_g1[BSR*HH];
__device__ float g_c0a[BSR*HH];   // bat0 split-K x4 partials
__device__ float g_c0b[BSR*HH];
__device__ float g_c0c[BSR*HH];
__device__ float g_c0d[BSR*HH];
__device__ float g_c1a[BSR*HH];   // bat1 split-K x4 partials
__device__ float g_c1b[BSR*HH];
__device__ float g_c1c[BSR*HH];
__device__ float g_c1d[BSR*HH];

// ---------------- prep ------------------------------------------------------
__global__ void prep_weights(const float* __restrict__ Wh, const float* __restrict__ bh) {
    int t = threadIdx.x;
    const int WHC = 2*HH + EE;
    if (t < EE) {
        float s = 0.f;
        for (int f = 0; f < EE; f++) s += Wh[f*WHC + t];
        g_we[t] = s;
    }
    if (t < HH) {
        float a = 0.f, b = 0.f;
        for (int f = 0; f < EE; f++) {
            a += Wh[f*WHC + EE + t];
            b += Wh[f*WHC + EE + HH + t];
        }
        g_w1s[t] = a;
        g_w2s[t] = b;
    }
    if (t == 0) {
        float s = 0.f;
        for (int e = 0; e < EE; e++) s += bh[e];
        g_sbh = s;
    }
}

// ---- A-operand loaders: 8 k-values {kq..kq+3, kq+8..kq+11} ------------------
// ASRC 0: raw fp32 (float4) ; ASRC 1: g_g0 (float2) ; ASRC 2: g_g1 (float2)
template<int ASRC>
__device__ __forceinline__ void ldA8(float* ar, const float* __restrict__ A, int lda,
                                     int m, int kq, int K) {
    if (ASRC == 0) {
        const float* p = A + (size_t)m * lda;
        #pragma unroll
        for (int h = 0; h < 2; h++) {
            int k = kq + h*8;
            float4 v = (k < K) ? *(const float4*)(p + k) : make_float4(0.f,0.f,0.f,0.f);
            ar[h*4+0]=v.x; ar[h*4+1]=v.y; ar[h*4+2]=v.z; ar[h*4+3]=v.w;
        }
    } else {
        const float* p = ((ASRC==1) ? g_g0 : g_g1) + (size_t)m * HH;
        #pragma unroll
        for (int h = 0; h < 2; h++) {
            #pragma unroll
            for (int t = 0; t < 2; t++) {
                int k = kq + h*8 + t*2;
                float2 v = (k < K) ? *(const float2*)(p + k) : make_float2(0.f,0.f);
                ar[h*4 + t*2] = v.x; ar[h*4 + t*2 + 1] = v.y;
            }
        }
    }
}

// ======= NT GEMM core: 64x32 tile, 128 thr, 4x4 micro (round-5 proven) ======
template<int ASRC>
__device__ __forceinline__ void ntB(
    const float* __restrict__ A, int lda, int K,
    const float* __restrict__ W, int ldw, int N,
    int m0, int n0,
    const float* __restrict__ biasC, const float* __restrict__ Cadd,
    float* __restrict__ C, int ldc)
{
    __shared__ __align__(16) float As[16][68];
    __shared__ __align__(16) float Ws[16][36];
    int tid = threadIdx.x;
    int arow = tid >> 1, aq = (tid & 1) * 4;
    int wrow = tid >> 2, wq = (tid & 3) * 2;
    int tx = tid & 7, ty = tid >> 3;
    int NIT = (K + 15) >> 4;

    int mA = m0 + arow;
    int nW = n0 + wrow;
    bool nok = nW < N;
    const float* Wrow = W + (size_t)(nok ? nW : 0) * ldw;

    float ar[8], wr[4];
    float acc[4][4] = {};

    ldA8<ASRC>(ar, A, lda, mA, aq, K);
    #pragma unroll
    for (int h = 0; h < 2; h++) {
        int k = wq + h*8;
        float2 v = (nok && k < K) ? *(const float2*)(Wrow + k) : make_float2(0.f,0.f);
        wr[h*2] = v.x; wr[h*2+1] = v.y;
    }

    for (int it = 0; it < NIT; it++) {
        __syncthreads();
        #pragma unroll
        for (int h = 0; h < 2; h++)
            #pragma unroll
            for (int j = 0; j < 4; j++)
                As[aq + h*8 + j][arow] = ar[h*4 + j];
        #pragma unroll
        for (int h = 0; h < 2; h++)
            #pragma unroll
            for (int j = 0; j < 2; j++)
                Ws[wq + h*8 + j][wrow] = wr[h*2 + j];
        __syncthreads();
        if (it + 1 < NIT) {
            int k0 = (it + 1) * 16;
            ldA8<ASRC>(ar, A, lda, mA, k0 + aq, K);
            #pragma unroll
            for (int h = 0; h < 2; h++) {
                int k = k0 + wq + h*8;
                float2 v = (nok && k < K) ? *(const float2*)(Wrow + k) : make_float2(0.f,0.f);
                wr[h*2] = v.x; wr[h*2+1] = v.y;
            }
        }
        #pragma unroll
        for (int kk = 0; kk < 16; kk++) {
            float4 a = *(const float4*)&As[kk][ty*4];
            float4 w = *(const float4*)&Ws[kk][tx*4];
            float am[4] = {a.x,a.y,a.z,a.w};
            float wm[4] = {w.x,w.y,w.z,w.w};
            #pragma unroll
            for (int i = 0; i < 4; i++)
                #pragma unroll
                for (int j = 0; j < 4; j++)
                    acc[i][j] = fmaf(am[i], wm[j], acc[i][j]);
        }
    }

    #pragma unroll
    for (int i = 0; i < 4; i++) {
        int m = m0 + ty*4 + i;
        #pragma unroll
        for (int j = 0; j < 4; j++) {
            int n = n0 + tx*4 + j;
            if (n < N) {
                float v = acc[i][j];
                if (biasC) v += biasC[n];
                if (Cadd) v += Cadd[(size_t)m*ldc + n];
                C[(size_t)m*ldc + n] = v;
            }
        }
    }
}

// ======= stage1: Q, PX, OX GEMMs first, then adj reduction (round-5 order) ==
#define QB 120
#define PXB 120
#define OXB 240
#define GEMMB (QB+PXB+OXB)      /* 480 */
#define ADJ_RPB 64
#define ADJ_BLOCKS (BBATCH*SSZ*SSZ/ADJ_RPB)   /* 9216 */

__global__ __launch_bounds__(128) void stage1(
    const float* __restrict__ adj, const float* __restrict__ X,
    const float* __restrict__ W0, const float* __restrict__ W1,
    const float* __restrict__ Wout, const float* __restrict__ bout)
{
    int bx = blockIdx.x;
    if (bx < QB) {               // Q = X @ W0^T
        ntB<0>(X, DD, DD, W0, DD, HH, (bx/5)*64, (bx%5)*32,
               nullptr, nullptr, g_Q, HH);
        return;
    }
    if (bx < QB + PXB) {         // PX = X @ W1[:, :300]^T
        int t = bx - QB;
        ntB<0>(X, DD, DD, W1, D1, HH, (t/5)*64, (t%5)*32,
               nullptr, nullptr, g_P, HH);
        return;
    }
    if (bx < GEMMB) {            // OX = X @ Wout^T + bout
        int t = bx - QB - PXB;
        ntB<0>(X, DD, DD, Wout, DD, DD, (t/10)*64, (t%10)*32,
               bout, nullptr, g_OX, DD);
        return;
    }
    // ---- adj reduction: 64 rows/block, smem-staged ----
    __shared__ float buf[ADJ_RPB][51];
    __shared__ float swe[EE];
    int tid = threadIdx.x;
    if (tid < EE) swe[tid] = g_we[tid];
    size_t r0 = (size_t)(bx - GEMMB) * ADJ_RPB;
    const float4* src = (const float4*)(adj + r0 * EE);
    for (int idx = tid; idx < ADJ_RPB*EE/4; idx += 128) {
        float4 v = src[idx];
        int g = idx * 4;
        buf[(g  )/EE][(g  )%EE] = v.x;
        buf[(g+1)/EE][(g+1)%EE] = v.y;
        buf[(g+2)/EE][(g+2)%EE] = v.z;
        buf[(g+3)/EE][(g+3)%EE] = v.w;
    }
    __syncthreads();
    if (tid < ADJ_RPB) {
        float s0 = 0.f, s1 = 0.f;
        #pragma unroll 10
        for (int e = 0; e < EE; e++) {
            float v = buf[tid][e];
            s0 += v;
            s1 = fmaf(v, swe[e], s1);
        }
        g_A0[r0 + tid] = s0;
        g_A1[r0 + tid] = s1;
    }
}

// ======= bat: batched NN GEMM, split-K x4, 64x32 tile (round-15 proven) =====
// grid (5, 6, 16): z = b*4 + quarter, K = 96 per quarter (6 chunks of 16)
// MODE 0: partial of A0@Q ; MODE 1: partial of Atilde1@P (rank-2 fold in A)
template<int MODE>
__global__ __launch_bounds__(128) void bat() {
    __shared__ __align__(16) float As[16][68];
    __shared__ __align__(8)  float Bs[16][34];
    int zc = blockIdx.z;
    int b = zc >> 2, quarter = zc & 3;
    const float* A  = (MODE==0 ? g_A0 : g_A1) + (size_t)b * SSZ * SSZ;
    const float* Bm = (MODE==0 ? g_Q  : g_P ) + (size_t)b * SSZ * HH;
    float* Cp = (MODE==0)
        ? (quarter==0 ? g_c0a : quarter==1 ? g_c0b : quarter==2 ? g_c0c : g_c0d)
        : (quarter==0 ? g_c1a : quarter==1 ? g_c1b : quarter==2 ? g_c1c : g_c1d);
    int m0 = blockIdx.y * 64, n0 = blockIdx.x * 32;
    int tid = threadIdx.x;
    int arow = tid >> 1, aq = (tid & 1) * 4;
    int bk = tid >> 3, bn = (tid & 7) * 4;
    int tx = tid & 7, ty = tid >> 3;
    int kbase = quarter * 96;

    const float* Arow = A + (size_t)(m0 + arow) * SSZ + kbase;
    const float* s1p = g_s1 + b * SSZ + kbase;
    float s2i = 0.f;
    if (MODE == 1) s2i = g_s2[b*SSZ + m0 + arow] + g_sbh;

    float ar[8], br[4];
    float acc[4][4] = {};

    // prefetch it=0
    #pragma unroll
    for (int h = 0; h < 2; h++) {
        int k = aq + h*8;
        float4 v = *(const float4*)(Arow + k);
        if (MODE == 1) {
            float4 s = *(const float4*)(s1p + k);
            v.x += s.x + s2i; v.y += s.y + s2i; v.z += s.z + s2i; v.w += s.w + s2i;
        }
        ar[h*4]=v.x; ar[h*4+1]=v.y; ar[h*4+2]=v.z; ar[h*4+3]=v.w;
    }
    {
        const float* p = Bm + (size_t)(kbase + bk) * HH + n0 + bn;
        #pragma unroll
        for (int t = 0; t < 2; t++) {
            int n = n0 + bn + 2*t;
            float2 v = (n < HH) ? *(const float2*)(p + 2*t) : make_float2(0.f,0.f);
            br[2*t] = v.x; br[2*t+1] = v.y;
        }
    }

    for (int it = 0; it < 6; it++) {
        __syncthreads();
        #pragma unroll
        for (int h = 0; h < 2; h++)
            #pragma unroll
            for (int j = 0; j < 4; j++)
                As[aq + h*8 + j][arow] = ar[h*4 + j];
        #pragma unroll
        for (int j = 0; j < 4; j++) Bs[bk][bn + j] = br[j];
        __syncthreads();
        if (it + 1 < 6) {
            int k0 = (it + 1) * 16;
            #pragma unroll
            for (int h = 0; h < 2; h++) {
                int k = k0 + aq + h*8;
                float4 v = *(const float4*)(Arow + k);
                if (MODE == 1) {
                    float4 s = *(const float4*)(s1p + k);
                    v.x += s.x + s2i; v.y += s.y + s2i; v.z += s.z + s2i; v.w += s.w + s2i;
                }
                ar[h*4]=v.x; ar[h*4+1]=v.y; ar[h*4+2]=v.z; ar[h*4+3]=v.w;
            }
            const float* p = Bm + (size_t)(kbase + k0 + bk) * HH + n0 + bn;
            #pragma unroll
            for (int t = 0; t < 2; t++) {
                int n = n0 + bn + 2*t;
                float2 v = (n < HH) ? *(const float2*)(p + 2*t) : make_float2(0.f,0.f);
                br[2*t] = v.x; br[2*t+1] = v.y;
            }
        }
        #pragma unroll
        for (int kk = 0; kk < 16; kk++) {
            float4 a = *(const float4*)&As[kk][ty*4];
            float2 b0v = *(const float2*)&Bs[kk][tx*4];
            float2 b1v = *(const float2*)&Bs[kk][tx*4 + 2];
            float am[4] = {a.x,a.y,a.z,a.w};
            float wm[4] = {b0v.x,b0v.y,b1v.x,b1v.y};
            #pragma unroll
            for (int i = 0; i < 4; i++)
                #pragma unroll
                for (int j = 0; j < 4; j++)
                    acc[i][j] = fmaf(am[i], wm[j], acc[i][j]);
        }
    }

    #pragma unroll
    for (int i = 0; i < 4; i++) {
        int row = b*SSZ + m0 + ty*4 + i;
        #pragma unroll
        for (int j = 0; j < 4; j++) {
            int n = n0 + tx*4 + j;
            if (n < HH) Cp[(size_t)row*HH + n] = acc[i][j];
        }
    }
}

// ======= combine: g = relu((ca+cb+cc+cd)/E + base + 2*bias), elementwise ====
// MODE 0: g0 from c0*, base=Q ; MODE 1: g1 from c1*, base=P
// grid 900 x 128 threads, float2 per thread (BSR*HH = 230400 elements)
template<int MODE>
__global__ __launch_bounds__(128) void combine(const float* __restrict__ bias) {
    __shared__ float sb[HH];
    int tid = threadIdx.x;
    for (int i = tid; i < HH; i += 128) sb[i] = bias[i];
    __syncthreads();
    int i2 = blockIdx.x * 128 + tid;
    size_t e = (size_t)i2 * 2;
    int k = (int)(e % HH);            // e even, HH even -> k even, pair in-row
    const float* pa = (MODE==0) ? g_c0a : g_c1a;
    const float* pb = (MODE==0) ? g_c0b : g_c1b;
    const float* pc = (MODE==0) ? g_c0c : g_c1c;
    const float* pd = (MODE==0) ? g_c0d : g_c1d;
    const float* pq = (MODE==0) ? g_Q   : g_P;
    float*       pg = (MODE==0) ? g_g0  : g_g1;
    float2 a = *(const float2*)(pa + e);
    float2 b = *(const float2*)(pb + e);
    float2 c = *(const float2*)(pc + e);
    float2 d = *(const float2*)(pd + e);
    float2 q = *(const float2*)(pq + e);
    float2 r;
    r.x = fmaxf(fmaf((a.x + b.x) + (c.x + d.x), INVE, q.x + 2.f*sb[k]),   0.f);
    r.y = fmaxf(fmaf((a.y + b.y) + (c.y + d.y), INVE, q.y + 2.f*sb[k+1]), 0.f);
    *(float2*)(pg + e) = r;
}

// ======= stage3: P += g0@W1b^T ; OX += g0@WoutA^T ; s1/s2 (reads g_g0) ======
#define PAB 120
#define OAB 240
__global__ __launch_bounds__(128) void stage3(const float* __restrict__ W1,
                                              const float* __restrict__ Wout) {
    int bx = blockIdx.x;
    if (bx < PAB) {
        ntB<1>(nullptr, 0, HH, W1 + DD, D1, HH, (bx/5)*64, (bx%5)*32,
               nullptr, g_P, g_P, HH);
        return;
    }
    if (bx < PAB + OAB) {
        int t = bx - PAB;
        ntB<1>(nullptr, 0, HH, Wout, DD, DD, (t/10)*64, (t%10)*32,
               nullptr, g_OX, g_OX, DD);
        return;
    }
    // s1/s2: thread per row, direct g_g0 reads
    __shared__ float sw1[HH], sw2[HH];
    int tid = threadIdx.x;
    for (int i = tid; i < HH; i += 128) {
        sw1[i] = g_w1s[i]; sw2[i] = g_w2s[i];
    }
    __syncthreads();
    int row = (bx - PAB - OAB) * 128 + tid;
    const float* g = g_g0 + (size_t)row * HH;
    float a1 = 0.f, a2 = 0.f;
    for (int k = 0; k < HH; k += 2) {
        float2 v = *(const float2*)(g + k);
        a1 = fmaf(v.x, sw1[k], a1);  a1 = fmaf(v.y, sw1[k+1], a1);
        a2 = fmaf(v.x, sw2[k], a2);  a2 = fmaf(v.y, sw2[k+1], a2);
    }
    g_s1[row] = a1;
    g_s2[row] = a2;
}

// ======= stage6: out = OX + g1@WoutB^T ======================================
#define OXT 240
__global__ __launch_bounds__(128) void stage6(const float* __restrict__ Wout,
                                              float* __restrict__ out) {
    int bx = blockIdx.x;
    ntB<2>(nullptr, 0, HH, Wout + HH, DD, DD, (bx/10)*64, (bx%10)*32,
           nullptr, g_OX, out, DD);
}

// ======= launch =============================================================
extern "C" void kernel_launch(void* const* d_in, const int* in_sizes, int n_in,
                              void* d_out, int out_size) {
    const float* adj  = (const float*)d_in[0];
    const float* X    = (const float*)d_in[1];
    const float* W0   = (const float*)d_in[2];
    const float* b0   = (const float*)d_in[3];
    const float* W1   = (const float*)d_in[4];
    const float* b1   = (const float*)d_in[5];
    const float* Wh   = (const float*)d_in[6];
    const float* bh   = (const float*)d_in[7];
    const float* Wout = (const float*)d_in[8];
    const float* bout = (const float*)d_in[9];
    float* out = (float*)d_out;

    prep_weights<<<1, 256>>>(Wh, bh);

    // Q, PX, OX GEMMs overlapped with the 118MB adj streaming pass (GEMMs first)
    stage1<<<GEMMB + ADJ_BLOCKS, 128>>>(adj, X, W0, W1, Wout, bout);

    // split-K x4 partials of A0@Q
    bat<0><<<dim3(5, 6, 16), 128>>>();

    // g0 = relu((c0a+c0b+c0c+c0d)/E + Q + 2b0), materialized once
    combine<0><<<900, 128>>>(b0);

    // P += g0@W1b^T ; OX += g0@WoutA^T ; s1/s2  (single-stream g0 loads)
    stage3<<<PAB + OAB + 12, 128>>>(W1, Wout);

    // split-K x4 partials of Atilde1@P  (rank-2 correction folded into A)
    bat<1><<<dim3(5, 6, 16), 128>>>();

    // g1 materialized once
    combine<1><<<900, 128>>>(b1);

    // out = OX + g1@WoutB^T
    stage6<<<OXT, 128>>>(Wout, out);
}